// round 5
// baseline (speedup 1.0000x reference)
#include <cuda_runtime.h>

// DistanceTransformMap: exact 2-pass EDT + sqrt, FUSED into one persistent
// kernel with a software grid barrier between the row pass and column pass.
//
// Why: R2-R4 profiling showed per-block work is only a few hundred cycles;
// time was dominated by wave transitions (5.2 waves x ~2360cyc) and the
// second kernel launch (~5000cyc). 128 resident blocks x 6 tiles each in a
// single launch removes both.
//
// Exactness (unchanged): all field values g in [0, LARGE];
//  - once d^2 >= best, no candidate at distance >= d can win (g >= 0);
//  - pad candidates LARGE + d^2 > LARGE >= best0 never win;
//  - extra candidates inside a chunk-of-4 are valid upper bounds.
// All intermediates are exact integers < 2^24 in fp32 -> bit-exact vs ref.
//
// Barrier: monotonic counter (never reset) => correct across CUDA-graph
// replays (stream order serializes calls; each call consumes exactly GRID
// arrivals). 128 blocks <= 148 SMs => all blocks wave-1 resident => no
// deadlock. __threadfence before arrive publishes g_mid stores.

constexpr int Bn = 4;
constexpr int Hn = 384;
constexpr int Wn = 384;
constexpr float LARGE = 2.0f * (float)(Hn * Hn + Wn * Wn);  // 589824 > 383^2

constexpr int PAD = 388;           // d <= 386 in last chunk -> i+-d in [-386, 769]
constexpr int LW  = Wn + 2 * PAD;  // 1160 floats per padded line
constexpr int NT  = 768;           // threads per block (= 2 lines per tile)
constexpr int GRID = 128;          // all resident; 768/128 = 6 tiles per phase
constexpr int NPAIR = (Bn * Hn / 2) / GRID;  // 6

__device__ float g_mid[Bn * Wn * Hn];   // TRANSPOSED intermediate [b][x][y]
__device__ unsigned g_bar;              // monotonic grid-barrier counter

__device__ __forceinline__ float edt_search(const float* __restrict__ p) {
    float best = p[0];
    float df = 1.0f;
    int d = 1;
    while (df * df < best && d < Wn) {
        const float v0 = p[d],     v1 = p[-d];
        const float v2 = p[d + 1], v3 = p[-(d + 1)];
        const float v4 = p[d + 2], v5 = p[-(d + 2)];
        const float v6 = p[d + 3], v7 = p[-(d + 3)];
        const float e0 = df, e1 = df + 1.0f, e2 = df + 2.0f, e3 = df + 3.0f;
        float c0 = fminf(fmaf(e0, e0, v0), fmaf(e0, e0, v1));
        float c1 = fminf(fmaf(e1, e1, v2), fmaf(e1, e1, v3));
        float c2 = fminf(fmaf(e2, e2, v4), fmaf(e2, e2, v5));
        float c3 = fminf(fmaf(e3, e3, v6), fmaf(e3, e3, v7));
        best = fminf(best, fminf(fminf(c0, c1), fminf(c2, c3)));
        df += 4.0f;
        d += 4;
    }
    return best;
}

__device__ __forceinline__ void grid_barrier() {
    __threadfence();                       // publish my stores device-wide
    __syncthreads();
    if (threadIdx.x == 0) {
        const unsigned old = atomicAdd(&g_bar, 1u);
        const unsigned target = old - (old % GRID) + GRID;
        while (atomicAdd(&g_bar, 0u) < target) {
            __nanosleep(64);
        }
        __threadfence();                   // acquire side
    }
    __syncthreads();
}

__global__ __launch_bounds__(NT) void edt_fused(const float* __restrict__ mask,
                                                float* __restrict__ out) {
    __shared__ float sh[2 * LW];
    const int t = threadIdx.x;
    const int blk = blockIdx.x;
    const int l = (t >= Wn) ? 1 : 0;       // line within tile (Hn == Wn)
    const int i = t - l * Wn;              // position within line
    float* const myp = &sh[l * LW + PAD + i];

    // Fill LARGE pads once (fixed regions, never overwritten).
    for (int k = t; k < 2 * 2 * PAD; k += NT) {
        const int ln = k / (2 * PAD);
        const int off = k - ln * 2 * PAD;
        const int idx = (off < PAD) ? off : (LW - 2 * PAD + off);
        sh[ln * LW + idx] = LARGE;
    }

    // ---- Phase 1: row EDT (mask -> g_mid transposed) ----
    float v = mask[(size_t)(blk * NPAIR) * 2 * Wn + t];       // prefetch tile 0
#pragma unroll
    for (int it = 0; it < NPAIR; ++it) {
        const int pair = blk * NPAIR + it;
        float vn = 0.0f;
        if (it + 1 < NPAIR)
            vn = mask[(size_t)(pair + 1) * 2 * Wn + t];       // prefetch next

        *myp = (v > 0.5f) ? LARGE : 0.0f;
        __syncthreads();
        const float best = edt_search(myp);

        const int r = pair * 2 + l;                            // r = b*Hn + y
        const int b = r / Hn;
        const int y = r - b * Hn;
        g_mid[((size_t)b * Wn + i) * Hn + y] = best;           // scatter (latency-free)
        __syncthreads();                                       // sh reads done
        v = vn;
    }

    grid_barrier();                                            // all g_mid visible

    // ---- Phase 2: column EDT (g_mid -> out) ----
    v = g_mid[(size_t)(blk * NPAIR) * 2 * Hn + t];             // coalesced prefetch
#pragma unroll
    for (int it = 0; it < NPAIR; ++it) {
        const int pair = blk * NPAIR + it;
        float vn = 0.0f;
        if (it + 1 < NPAIR)
            vn = g_mid[(size_t)(pair + 1) * 2 * Hn + t];

        *myp = v;
        __syncthreads();
        const float res = sqrtf(edt_search(myp));

        const int c = pair * 2 + l;                            // c = b*Wn + x
        const int b = c / Wn;
        const int x = c - b * Wn;
        out[((size_t)b * Hn + i) * Wn + x] = res;              // scatter (latency-free)
        __syncthreads();
        v = vn;
    }
}

extern "C" void kernel_launch(void* const* d_in, const int* in_sizes, int n_in,
                              void* d_out, int out_size) {
    const float* mask = (const float*)d_in[0];
    float* out = (float*)d_out;
    (void)in_sizes; (void)n_in; (void)out_size;

    edt_fused<<<GRID, NT>>>(mask, out);
}

// round 6
// speedup vs baseline: 1.1193x; 1.1193x over previous
#include <cuda_runtime.h>

// DistanceTransformMap: exact 2-pass EDT + sqrt.
// One line per WARP (no block-level syncs), 12 searches per thread.
// Near window d<=4 evaluated unconditionally (exact: extra candidates are
// upper bounds) with compile-time d^2 -> branch-free, 8 independent LDS per
// search, fully unrolled over 12 searches => deep MLP. Rare far searches
// (best > 25) take a clamped-index slow loop.
//
// Clamp exactness (PAD=8, line width 400): for any d in the slow loop,
// idx = clamp(i+PAD+-(d..d+3), 0, 399). If the logical index is in bounds it
// is unchanged (i-d>=0 -> idx>=PAD; i+d<=383 -> idx<=391). If out of bounds,
// the clamped slot is always a LARGE pad or further-out pad (left pads 0..7,
// right pads 392..399), and LARGE + d^2 > LARGE >= best0 never wins. Hence
// identical to the reference brute force; all values are exact integers
// < 2^24 in fp32 -> bit-exact (sqrt at the end only).

constexpr int Bn = 4;
constexpr int Hn = 384;
constexpr int Wn = 384;
constexpr int N  = 384;                     // line length (H == W)
constexpr float LARGE = 2.0f * (float)(Hn * Hn + Wn * Wn);  // 589824 > 383^2

constexpr int PAD = 8;
constexpr int LWD = N + 2 * PAD;            // 400
constexpr int WPB = 12;                     // warps (= lines) per block
constexpr int NT  = WPB * 32;               // 384 threads
constexpr int GRID = (Bn * Hn) / WPB;       // 128 -> single wave, balanced

__device__ float g_mid[Bn * Wn * Hn];       // TRANSPOSED intermediate [b][x][y]

__device__ __forceinline__ float edt_search(const float* __restrict__ row, int i) {
    const float* p = row + PAD + i;
    // Unconditional near window d = 0..4 (compile-time d^2).
    float best = p[0];
    const float c1 = fminf(p[1], p[-1]) + 1.0f;
    const float c2 = fminf(p[2], p[-2]) + 4.0f;
    const float c3 = fminf(p[3], p[-3]) + 9.0f;
    const float c4 = fminf(p[4], p[-4]) + 16.0f;
    best = fminf(best, fminf(fminf(c1, c2), fminf(c3, c4)));
    if (best > 25.0f) {                      // rare: continue outward, exact
        float df = 5.0f;
        int d = 5;
        const int ip = i + PAD;
        while (df * df < best && d < N) {
#pragma unroll
            for (int u = 0; u < 4; ++u) {
                const int jr = min(ip + d + u, LWD - 1);
                const int jl = max(ip - d - u, 0);
                const float e = df + (float)u;
                best = fminf(best, fmaf(e, e, fminf(row[jr], row[jl])));
            }
            df += 4.0f;
            d += 4;
        }
    }
    return best;
}

// Pass 1: row EDT. Warp w owns line L = blk*12 + w. Coalesced load,
// transposed scatter store (stores are latency-free).
__global__ __launch_bounds__(NT) void edt_pass1(const float* __restrict__ mask) {
    __shared__ float sh[WPB][LWD];
    const int w = threadIdx.x >> 5, lane = threadIdx.x & 31;
    const int L = blockIdx.x * WPB + w;      // L = b*Hn + y
    float* const row = sh[w];

    float v[12];
#pragma unroll
    for (int k = 0; k < 12; ++k)
        v[k] = mask[(size_t)L * N + lane + 32 * k];
    if (lane < PAD) { row[lane] = LARGE; row[LWD - PAD + lane] = LARGE; }
#pragma unroll
    for (int k = 0; k < 12; ++k)
        row[PAD + lane + 32 * k] = (v[k] > 0.5f) ? LARGE : 0.0f;
    __syncwarp();

    const int b = L / Hn, y = L - b * Hn;
    float* const dst = g_mid + (size_t)b * Wn * Hn + y;
#pragma unroll
    for (int k = 0; k < 12; ++k) {
        const int i = lane + 32 * k;
        dst[(size_t)i * Hn] = edt_search(row, i);   // [b][i][y] scatter
    }
}

// Pass 2: column EDT on transposed mid. Warp w owns column-line C = blk*12+w.
// Coalesced load, scatter store to natural layout, sqrt at the end.
__global__ __launch_bounds__(NT) void edt_pass2(float* __restrict__ out) {
    __shared__ float sh[WPB][LWD];
    const int w = threadIdx.x >> 5, lane = threadIdx.x & 31;
    const int C = blockIdx.x * WPB + w;      // C = b*Wn + x
    float* const row = sh[w];

    float v[12];
#pragma unroll
    for (int k = 0; k < 12; ++k)
        v[k] = g_mid[(size_t)C * N + lane + 32 * k];
    if (lane < PAD) { row[lane] = LARGE; row[LWD - PAD + lane] = LARGE; }
#pragma unroll
    for (int k = 0; k < 12; ++k)
        row[PAD + lane + 32 * k] = v[k];
    __syncwarp();

    const int b = C / Wn, x = C - b * Wn;
    float* const dst = out + (size_t)b * Hn * Wn + x;
#pragma unroll
    for (int k = 0; k < 12; ++k) {
        const int i = lane + 32 * k;         // y
        dst[(size_t)i * Wn] = sqrtf(edt_search(row, i));
    }
}

extern "C" void kernel_launch(void* const* d_in, const int* in_sizes, int n_in,
                              void* d_out, int out_size) {
    const float* mask = (const float*)d_in[0];
    float* out = (float*)d_out;
    (void)in_sizes; (void)n_in; (void)out_size;

    edt_pass1<<<GRID, NT>>>(mask);
    edt_pass2<<<GRID, NT>>>(out);
}

// round 7
// speedup vs baseline: 1.7589x; 1.5714x over previous
#include <cuda_runtime.h>

// DistanceTransformMap: exact 2-pass EDT + sqrt.
//
// Pass 1 (rows, binary input): BIT-TRICK distance. Each warp owns a line;
// __ballot_sync packs the line's zero-pixel mask into 12 words held by every
// lane. Nearest zero left/right = __ffs/__clz on shifted words (+ word scan,
// expected ~1 iter). Exact for ALL inputs: d in [0,383] -> d*d exact in fp32;
// no zero in row -> LARGE, matching the reference min (attained at j=i).
// No shared memory, no search loop, coalesced load+store (natural layout).
//
// Pass 2 (columns): expanding-window search per output. Near window d<=4
// evaluated unconditionally (extra candidates are upper bounds -> exact),
// batched 3 searches x 9 independent LDS for MLP. Rare far case (best>25)
// takes a clamped-index loop: clamped slots always land on LARGE pads
// (left pads 0..7, right 392..399; in-range indices 8..391 unaltered), and
// LARGE + d^2 > LARGE >= best0 never wins -> exact.
// Block = 24 warps, 12 columns, 2 warps/column; tile loads (12-float rows)
// and smem-staged tile stores avoid 32-sector scatters.
// All intermediates are exact integers < 2^24 in fp32 -> bit-exact vs ref.

constexpr int Bn = 4;
constexpr int Hn = 384;
constexpr int Wn = 384;
constexpr int N  = 384;
constexpr float LARGE = 2.0f * (float)(Hn * Hn + Wn * Wn);  // 589824 > 383^2

__device__ float g_mid[Bn * Hn * Wn];   // NATURAL layout [b][y][x]

// ---------------- Pass 1: bit-trick row EDT ----------------
__global__ __launch_bounds__(384) void edt_pass1(const float* __restrict__ mask) {
    const int w = threadIdx.x >> 5, lane = threadIdx.x & 31;
    const int L = blockIdx.x * 12 + w;            // global row index (b*Hn+y)
    const size_t base = (size_t)L * N;

    float v[12];
#pragma unroll
    for (int k = 0; k < 12; ++k)
        v[k] = mask[base + lane + 32 * k];        // coalesced

    unsigned m[12];
#pragma unroll
    for (int k = 0; k < 12; ++k)
        m[k] = __ballot_sync(0xffffffffu, v[k] <= 0.5f);  // zero-pixel bits

#pragma unroll
    for (int k = 0; k < 12; ++k) {
        // right: nearest set bit at position >= p
        int dr = 1000;
        const unsigned xr = m[k] >> lane;         // bit0 = self
        if (xr) {
            dr = __ffs(xr) - 1;
        } else {
            int off = 32 - lane;
            for (int q = k + 1; q < 12; ++q) {
                if (m[q]) { dr = off + __ffs(m[q]) - 1; break; }
                off += 32;
            }
        }
        // left: nearest set bit at position <= p
        int dl = 1000;
        const unsigned xl = m[k] << (31 - lane);  // bit31 = self
        if (xl) {
            dl = __clz(xl);
        } else {
            int off = lane + 1;
            for (int q = k - 1; q >= 0; --q) {
                if (m[q]) { dl = off + __clz(m[q]); break; }
                off += 32;
            }
        }
        const int d = min(dl, dr);
        const float res = (d <= 383) ? (float)(d * d) : LARGE;
        g_mid[base + lane + 32 * k] = res;        // coalesced, natural layout
    }
}

// ---------------- Pass 2: column EDT ----------------
constexpr int PAD = 8;
constexpr int LWD = N + 2 * PAD;    // 400 valid slots per line
constexpr int LWP = 403;            // row stride (odd -> conflict-free fill)
constexpr int NT2 = 768;            // 24 warps: 2 warps per column-line

__device__ __forceinline__ float near_far(const float* __restrict__ row,
                                          float best, int i) {
    // best already covers d<=4; continue outward only if needed (rare).
    if (best > 25.0f) {
        float df = 5.0f;
        int d = 5;
        const int ip = i + PAD;
        while (df * df < best && d < N) {
#pragma unroll
            for (int u = 0; u < 4; ++u) {
                const int jr = min(ip + d + u, LWD - 1);
                const int jl = max(ip - d - u, 0);
                const float e = df + (float)u;
                best = fminf(best, fmaf(e, e, fminf(row[jr], row[jl])));
            }
            df += 4.0f;
            d += 4;
        }
    }
    return best;
}

__global__ __launch_bounds__(NT2, 1) void edt_pass2(float* __restrict__ out) {
    __shared__ float sh_line[12 * LWP];           // 12 padded column-lines
    __shared__ float sh_o[N * 13];                // staged output tile [y][c]
    const int t = threadIdx.x;
    const int b = blockIdx.x >> 5;                // 32 strips per batch
    const int x0 = (blockIdx.x & 31) * 12;

    // Tile load: idx = t + 768*r ; c = t%12 (const per thread), y = t/12+64r.
    const int c_ld = t % 12;
    const int y_ld = t / 12;
    const float* __restrict__ src = g_mid + ((size_t)b * Hn) * Wn + x0 + c_ld;
#pragma unroll
    for (int r = 0; r < 6; ++r) {
        const int y = y_ld + 64 * r;
        sh_line[c_ld * LWP + PAD + y] = src[(size_t)y * Wn];
    }
    if (t < 12 * 8) {                             // LARGE pads
        const int c = t >> 3, o = t & 7;
        sh_line[c * LWP + o] = LARGE;
        sh_line[c * LWP + LWD - PAD + o] = LARGE;
    }
    __syncthreads();

    const int w = t >> 5, lane = t & 31;
    const int cl = (w < 12) ? w : (w - 12);       // column-line within tile
    const int half = (w < 12) ? 0 : 192;
    const float* __restrict__ row = &sh_line[cl * LWP];
    const int ibase = half + lane;

    float best[6];
#pragma unroll
    for (int g = 0; g < 6; g += 3) {              // groups of 3 searches
        float a[3][9];
#pragma unroll
        for (int s = 0; s < 3; ++s) {
            const float* p = row + PAD + ibase + 32 * (g + s);
            a[s][0] = p[0];
            a[s][1] = p[1];  a[s][2] = p[-1];
            a[s][3] = p[2];  a[s][4] = p[-2];
            a[s][5] = p[3];  a[s][6] = p[-3];
            a[s][7] = p[4];  a[s][8] = p[-4];
        }
#pragma unroll
        for (int s = 0; s < 3; ++s) {
            const float c1 = fminf(a[s][1], a[s][2]) + 1.0f;
            const float c2 = fminf(a[s][3], a[s][4]) + 4.0f;
            const float c3 = fminf(a[s][5], a[s][6]) + 9.0f;
            const float c4 = fminf(a[s][7], a[s][8]) + 16.0f;
            best[g + s] = fminf(a[s][0],
                          fminf(fminf(c1, c2), fminf(c3, c4)));
        }
    }
#pragma unroll
    for (int s = 0; s < 6; ++s)
        best[s] = near_far(row, best[s], ibase + 32 * s);

    // Stage results: sh_o[y][cl], lanes hit consecutive y (stride 13, clean).
#pragma unroll
    for (int s = 0; s < 6; ++s)
        sh_o[(ibase + 32 * s) * 13 + cl] = sqrtf(best[s]);
    __syncthreads();

    // Tile store, same mapping as the load (6 sectors per warp-store).
    float* __restrict__ dst = out + ((size_t)b * Hn) * Wn + x0 + c_ld;
#pragma unroll
    for (int r = 0; r < 6; ++r) {
        const int y = y_ld + 64 * r;
        dst[(size_t)y * Wn] = sh_o[y * 13 + c_ld];
    }
}

extern "C" void kernel_launch(void* const* d_in, const int* in_sizes, int n_in,
                              void* d_out, int out_size) {
    const float* mask = (const float*)d_in[0];
    float* out = (float*)d_out;
    (void)in_sizes; (void)n_in; (void)out_size;

    edt_pass1<<<Bn * Hn / 12, 384>>>(mask);
    edt_pass2<<<Bn * Wn / 12, NT2>>>(out);
}